// round 1
// baseline (speedup 1.0000x reference)
#include <cuda_runtime.h>

#define NN 100000
#define EE 1600000
#define DD 128
#define EPS 1e-5f

// ---------------- device scratch (static, no runtime alloc) ----------------
__device__ int   g_cnt[NN];          // degree counters / fill cursors
__device__ int   g_rowptr[NN + 1];   // CSR row pointers (by dst)
__device__ int   g_csr[EE];          // CSR column (src) indices
__device__ float g_agg[(size_t)NN * DD];
__device__ float g_h1 [(size_t)NN * DD];
__device__ float g_h2 [(size_t)NN * DD];

typedef unsigned long long u64;

__device__ __forceinline__ u64 pack2(float x, float y) {
    u64 r; asm("mov.b64 %0, {%1, %2};" : "=l"(r) : "f"(x), "f"(y)); return r;
}
__device__ __forceinline__ void unpack2(u64 v, float &x, float &y) {
    asm("mov.b64 {%0, %1}, %2;" : "=f"(x), "=f"(y) : "l"(v));
}
__device__ __forceinline__ void fma2(u64 &d, u64 a, u64 b) {
    asm("fma.rn.f32x2 %0, %1, %2, %0;" : "+l"(d) : "l"(a), "l"(b));
}

// ---------------- CSR build ----------------
__global__ void k_zero() {
    int i = blockIdx.x * blockDim.x + threadIdx.x;
    if (i < NN) g_cnt[i] = 0;
}

__global__ void k_count(const int* __restrict__ dst) {
    int e = blockIdx.x * blockDim.x + threadIdx.x;
    if (e < EE) atomicAdd(&g_cnt[dst[e]], 1);
}

// single-block exclusive scan of g_cnt -> g_rowptr; also inits cursors
__global__ void k_scan() {
    __shared__ int ss[1024];
    int tid = threadIdx.x;
    const int chunk = (NN + 1023) / 1024;
    int start = tid * chunk;
    int stop  = min(start + chunk, NN);
    int s = 0;
    for (int i = start; i < stop; i++) s += g_cnt[i];
    ss[tid] = s;
    __syncthreads();
    #pragma unroll
    for (int off = 1; off < 1024; off <<= 1) {
        int v = (tid >= off) ? ss[tid - off] : 0;
        __syncthreads();
        ss[tid] += v;
        __syncthreads();
    }
    int run = (tid == 0) ? 0 : ss[tid - 1];
    for (int i = start; i < stop; i++) {
        int c = g_cnt[i];
        g_rowptr[i] = run;
        g_cnt[i]    = run;   // cursor init
        run += c;
    }
    if (tid == 0) g_rowptr[NN] = EE;
}

__global__ void k_fill(const int* __restrict__ src, const int* __restrict__ dst) {
    int e = blockIdx.x * blockDim.x + threadIdx.x;
    if (e < EE) {
        int pos = atomicAdd(&g_cnt[dst[e]], 1);
        g_csr[pos] = src[e];
    }
}

// ---------------- aggregation: one warp per node, lane owns 4 cols ----------------
__global__ __launch_bounds__(256) void k_agg(const float* __restrict__ h,
                                             float* __restrict__ agg) {
    int node = blockIdx.x * 8 + (threadIdx.x >> 5);
    if (node >= NN) return;
    int lane = threadIdx.x & 31;
    int beg = g_rowptr[node], end = g_rowptr[node + 1];
    float ax = 0.f, ay = 0.f, az = 0.f, aw = 0.f;
    int e = beg;
    for (; e + 4 <= end; e += 4) {
        int s0 = __ldg(&g_csr[e + 0]);
        int s1 = __ldg(&g_csr[e + 1]);
        int s2 = __ldg(&g_csr[e + 2]);
        int s3 = __ldg(&g_csr[e + 3]);
        float4 v0 = *(const float4*)(h + (size_t)s0 * DD + lane * 4);
        float4 v1 = *(const float4*)(h + (size_t)s1 * DD + lane * 4);
        float4 v2 = *(const float4*)(h + (size_t)s2 * DD + lane * 4);
        float4 v3 = *(const float4*)(h + (size_t)s3 * DD + lane * 4);
        ax += v0.x + v1.x + v2.x + v3.x;
        ay += v0.y + v1.y + v2.y + v3.y;
        az += v0.z + v1.z + v2.z + v3.z;
        aw += v0.w + v1.w + v2.w + v3.w;
    }
    for (; e < end; e++) {
        int s = __ldg(&g_csr[e]);
        float4 v = *(const float4*)(h + (size_t)s * DD + lane * 4);
        ax += v.x; ay += v.y; az += v.z; aw += v.w;
    }
    *(float4*)(agg + (size_t)node * DD + lane * 4) = make_float4(ax, ay, az, aw);
}

// ---------------- fused GEMM (agg@Wrel + h@Wroot + b) + epilogue ----------------
// mode 0: raw output (last layer)
// mode 1: relu -> LayerNorm
// mode 2: +residual(h) -> relu -> LayerNorm
__global__ __launch_bounds__(256) void k_gemm(
    const float* __restrict__ Aagg, const float* __restrict__ Hin,
    const float* __restrict__ Wrel, const float* __restrict__ Wroot,
    const float* __restrict__ brel,
    const float* __restrict__ gamma, const float* __restrict__ beta,
    float* __restrict__ out, int mode)
{
    __shared__ float aT[32][66];    // K-chunk x 64 rows (transposed, padded)
    __shared__ float wS[32][128];   // K-chunk x 128 cols

    int tid = threadIdx.x;
    int tx = tid & 31;        // column group: cols 4*tx .. 4*tx+3
    int ty = tid >> 5;        // row group: rows ty*8 .. ty*8+7
    int row0 = blockIdx.x * 64;

    // acc[i][c] = packed pair { out[2i][c], out[2i+1][c] } for rows ty*8+2i(+1)
    u64 acc[4][4];
    #pragma unroll
    for (int i = 0; i < 4; i++)
        #pragma unroll
        for (int c = 0; c < 4; c++) acc[i][c] = 0ull;

    for (int m = 0; m < 2; m++) {
        const float* Am = m ? Hin : Aagg;
        const float* Wm = m ? Wroot : Wrel;
        for (int kc = 0; kc < 4; kc++) {
            int k0 = kc * 32;
            __syncthreads();
            // stage A chunk transposed: aT[k][row]
            #pragma unroll
            for (int i = 0; i < 2; i++) {
                int idx = tid + i * 256;       // 0..511
                int row = idx >> 3, c4 = idx & 7;
                int gr = row0 + row;
                float4 v = make_float4(0.f, 0.f, 0.f, 0.f);
                if (gr < NN) v = *(const float4*)(Am + (size_t)gr * DD + k0 + c4 * 4);
                aT[c4 * 4 + 0][row] = v.x;
                aT[c4 * 4 + 1][row] = v.y;
                aT[c4 * 4 + 2][row] = v.z;
                aT[c4 * 4 + 3][row] = v.w;
            }
            // stage W chunk: wS[k][col]
            #pragma unroll
            for (int i = 0; i < 4; i++) {
                int idx = tid + i * 256;       // 0..1023 float4 units
                int r = idx >> 5, c4 = idx & 31;
                *(float4*)&wS[r][c4 * 4] =
                    *(const float4*)(Wm + (size_t)(k0 + r) * DD + c4 * 4);
            }
            __syncthreads();

            #pragma unroll
            for (int k = 0; k < 32; k++) {
                float4 w = *(const float4*)&wS[k][tx * 4];
                u64 w0 = pack2(w.x, w.x);
                u64 w1 = pack2(w.y, w.y);
                u64 w2 = pack2(w.z, w.z);
                u64 w3 = pack2(w.w, w.w);
                #pragma unroll
                for (int i = 0; i < 4; i++) {
                    u64 a = *(const u64*)&aT[k][ty * 8 + i * 2];  // rows 2i,2i+1 packed
                    fma2(acc[i][0], a, w0);
                    fma2(acc[i][1], a, w1);
                    fma2(acc[i][2], a, w2);
                    fma2(acc[i][3], a, w3);
                }
            }
        }
    }

    // ---------------- epilogue ----------------
    int rbase = row0 + ty * 8;
    if (rbase >= NN) return;   // whole-warp uniform

    float4 bv = *(const float4*)(brel  + tx * 4);
    float4 gv = *(const float4*)(gamma + tx * 4);
    float4 bt = *(const float4*)(beta  + tx * 4);

    #pragma unroll
    for (int i = 0; i < 4; i++) {
        int r0 = rbase + 2 * i;
        if (r0 >= NN) break;          // warp-uniform
        bool has1 = (r0 + 1 < NN);    // warp-uniform

        float xl0, xh0, xl1, xh1, xl2, xh2, xl3, xh3;
        unpack2(acc[i][0], xl0, xh0);
        unpack2(acc[i][1], xl1, xh1);
        unpack2(acc[i][2], xl2, xh2);
        unpack2(acc[i][3], xl3, xh3);
        xl0 += bv.x; xl1 += bv.y; xl2 += bv.z; xl3 += bv.w;
        xh0 += bv.x; xh1 += bv.y; xh2 += bv.z; xh3 += bv.w;

        if (mode == 0) {
            *(float4*)(out + (size_t)r0 * DD + tx * 4) = make_float4(xl0, xl1, xl2, xl3);
            if (has1)
                *(float4*)(out + (size_t)(r0 + 1) * DD + tx * 4) = make_float4(xh0, xh1, xh2, xh3);
            continue;
        }

        if (mode == 2) {
            float4 rl = *(const float4*)(Hin + (size_t)r0 * DD + tx * 4);
            xl0 += rl.x; xl1 += rl.y; xl2 += rl.z; xl3 += rl.w;
            if (has1) {
                float4 rh = *(const float4*)(Hin + (size_t)(r0 + 1) * DD + tx * 4);
                xh0 += rh.x; xh1 += rh.y; xh2 += rh.z; xh3 += rh.w;
            }
        }

        // ReLU
        xl0 = fmaxf(xl0, 0.f); xl1 = fmaxf(xl1, 0.f); xl2 = fmaxf(xl2, 0.f); xl3 = fmaxf(xl3, 0.f);
        xh0 = fmaxf(xh0, 0.f); xh1 = fmaxf(xh1, 0.f); xh2 = fmaxf(xh2, 0.f); xh3 = fmaxf(xh3, 0.f);

        // LayerNorm (row-wise over 128 = 32 lanes x 4)
        float s1 = xl0 + xl1 + xl2 + xl3;
        float s2 = xl0*xl0 + xl1*xl1 + xl2*xl2 + xl3*xl3;
        float t1 = xh0 + xh1 + xh2 + xh3;
        float t2 = xh0*xh0 + xh1*xh1 + xh2*xh2 + xh3*xh3;
        #pragma unroll
        for (int off = 16; off > 0; off >>= 1) {
            s1 += __shfl_xor_sync(0xffffffffu, s1, off);
            s2 += __shfl_xor_sync(0xffffffffu, s2, off);
            t1 += __shfl_xor_sync(0xffffffffu, t1, off);
            t2 += __shfl_xor_sync(0xffffffffu, t2, off);
        }
        const float inv = 1.f / 128.f;
        float mul = s1 * inv;
        float varl = fmaxf(s2 * inv - mul * mul, 0.f);
        float rsl = rsqrtf(varl + EPS);
        float muh = t1 * inv;
        float varh = fmaxf(t2 * inv - muh * muh, 0.f);
        float rsh = rsqrtf(varh + EPS);

        float4 ol = make_float4((xl0 - mul) * rsl * gv.x + bt.x,
                                (xl1 - mul) * rsl * gv.y + bt.y,
                                (xl2 - mul) * rsl * gv.z + bt.z,
                                (xl3 - mul) * rsl * gv.w + bt.w);
        *(float4*)(out + (size_t)r0 * DD + tx * 4) = ol;
        if (has1) {
            float4 oh = make_float4((xh0 - muh) * rsh * gv.x + bt.x,
                                    (xh1 - muh) * rsh * gv.y + bt.y,
                                    (xh2 - muh) * rsh * gv.z + bt.z,
                                    (xh3 - muh) * rsh * gv.w + bt.w);
            *(float4*)(out + (size_t)(r0 + 1) * DD + tx * 4) = oh;
        }
    }
}

// ---------------- launch ----------------
extern "C" void kernel_launch(void* const* d_in, const int* in_sizes, int n_in,
                              void* d_out, int out_size) {
    const float* in_feat = (const float*)d_in[0];
    const int*   ei      = (const int*)  d_in[1];
    const float* Wrel    = (const float*)d_in[2];
    const float* brel    = (const float*)d_in[3];
    const float* Wroot   = (const float*)d_in[4];
    const float* gamma   = (const float*)d_in[5];
    const float* beta    = (const float*)d_in[6];
    float*       out     = (float*)d_out;

    const int* src = ei;        // edge_index[0]
    const int* dst = ei + EE;   // edge_index[1]

    float *agg, *h1, *h2;
    cudaGetSymbolAddress((void**)&agg, g_agg);
    cudaGetSymbolAddress((void**)&h1,  g_h1);
    cudaGetSymbolAddress((void**)&h2,  g_h2);

    const int GB = (NN + 63) / 64;      // gemm blocks
    const int AB = (NN + 7) / 8;        // agg blocks (8 warps/block)
    const int EB = (EE + 255) / 256;

    // CSR build (every call: replay-deterministic work)
    k_zero <<<(NN + 255) / 256, 256>>>();
    k_count<<<EB, 256>>>(dst);
    k_scan <<<1, 1024>>>();
    k_fill <<<EB, 256>>>(src, dst);

    // layer 0: conv -> relu -> LN
    k_agg <<<AB, 256>>>(in_feat, agg);
    k_gemm<<<GB, 256>>>(agg, in_feat, Wrel, Wroot, brel, gamma, beta, h1, 1);
    // layer 1: conv -> +res -> relu -> LN
    k_agg <<<AB, 256>>>(h1, agg);
    k_gemm<<<GB, 256>>>(agg, h1, Wrel + DD*DD, Wroot + DD*DD, brel + DD, gamma, beta, h2, 2);
    // layer 2
    k_agg <<<AB, 256>>>(h2, agg);
    k_gemm<<<GB, 256>>>(agg, h2, Wrel + 2*DD*DD, Wroot + 2*DD*DD, brel + 2*DD, gamma, beta, h1, 2);
    // layer 3: conv only
    k_agg <<<AB, 256>>>(h1, agg);
    k_gemm<<<GB, 256>>>(agg, h1, Wrel + 3*DD*DD, Wroot + 3*DD*DD, brel + 3*DD, gamma, beta, out, 0);
}

// round 6
// speedup vs baseline: 1.1603x; 1.1603x over previous
#include <cuda_runtime.h>
#include <cuda_bf16.h>
#include <cstdint>

#define NN 100000
#define EE 1600000
#define DD 128
#define EPS 1e-5f

typedef unsigned short u16;
typedef unsigned int   u32;

// ---------------- device scratch ----------------
__device__ int g_cnt[NN];
__device__ int g_rowptr[NN + 1];
__device__ int g_csr[EE];
__device__ float g_h1[(size_t)NN * DD];
__device__ float g_h2[(size_t)NN * DD];
__device__ u16 g_WH[8 * DD * DD];            // [mat][n][k]  mat = 2*layer + (0=rel,1=root)
__device__ u16 g_WL[8 * DD * DD];
__device__ u16 g_ifH[(size_t)NN * DD], g_ifL[(size_t)NN * DD];
__device__ u16 g_pAH[(size_t)NN * DD], g_pAL[(size_t)NN * DD];
__device__ u16 g_pBH[(size_t)NN * DD], g_pBL[(size_t)NN * DD];
__device__ u16 g_agH[(size_t)NN * DD], g_agL[(size_t)NN * DD];

// ---------------- helpers ----------------
__device__ __forceinline__ u32 smem_u32(const void* p) {
    u32 a;
    asm("{ .reg .u64 t; cvta.to.shared.u64 t, %1; cvt.u32.u64 %0, t; }" : "=r"(a) : "l"(p));
    return a;
}

__device__ __forceinline__ void splitbf(float v, u16 &h, u16 &l) {
    __nv_bfloat16 hb = __float2bfloat16(v);
    float r = v - __bfloat162float(hb);
    __nv_bfloat16 lb = __float2bfloat16(r);
    h = *reinterpret_cast<u16*>(&hb);
    l = *reinterpret_cast<u16*>(&lb);
}

#define MMA(d, a, b0_, b1_)                                                     \
    asm volatile("mma.sync.aligned.m16n8k16.row.col.f32.bf16.bf16.f32 "         \
        "{%0,%1,%2,%3}, {%4,%5,%6,%7}, {%8,%9}, {%0,%1,%2,%3};"                 \
        : "+f"((d)[0]), "+f"((d)[1]), "+f"((d)[2]), "+f"((d)[3])                \
        : "r"((a)[0]), "r"((a)[1]), "r"((a)[2]), "r"((a)[3]), "r"(b0_), "r"(b1_))

#define CP16(dst, src)                                                          \
    asm volatile("cp.async.cg.shared.global [%0], [%1], 16;"                    \
                 :: "r"(dst), "l"(src) : "memory")
#define CP_COMMIT() asm volatile("cp.async.commit_group;" ::: "memory")
#define CP_WAIT0()  asm volatile("cp.async.wait_group 0;" ::: "memory")

// ---------------- CSR build ----------------
__global__ void k_zero() {
    int i = blockIdx.x * blockDim.x + threadIdx.x;
    if (i < NN) g_cnt[i] = 0;
}
__global__ void k_count(const int* __restrict__ dst) {
    int e = blockIdx.x * blockDim.x + threadIdx.x;
    if (e < EE) atomicAdd(&g_cnt[dst[e]], 1);
}
__global__ void k_scan() {
    __shared__ int ss[1024];
    int tid = threadIdx.x;
    const int chunk = (NN + 1023) / 1024;
    int start = tid * chunk, stop = min(start + chunk, NN);
    int s = 0;
    for (int i = start; i < stop; i++) s += g_cnt[i];
    ss[tid] = s;
    __syncthreads();
    #pragma unroll
    for (int off = 1; off < 1024; off <<= 1) {
        int v = (tid >= off) ? ss[tid - off] : 0;
        __syncthreads();
        ss[tid] += v;
        __syncthreads();
    }
    int run = (tid == 0) ? 0 : ss[tid - 1];
    for (int i = start; i < stop; i++) {
        int c = g_cnt[i];
        g_rowptr[i] = run;
        g_cnt[i] = run;
        run += c;
    }
    if (tid == 0) g_rowptr[NN] = EE;
}
__global__ void k_fill(const int* __restrict__ src, const int* __restrict__ dst) {
    int e = blockIdx.x * blockDim.x + threadIdx.x;
    if (e < EE) {
        int pos = atomicAdd(&g_cnt[dst[e]], 1);
        g_csr[pos] = src[e];
    }
}

// ---------------- W transpose + bf16 split ----------------
__global__ void k_prep(const float* __restrict__ Wrel, const float* __restrict__ Wroot) {
    int mat = blockIdx.x;                 // 0..7
    int l = mat >> 1, which = mat & 1;
    const float* W = (which ? Wroot : Wrel) + (size_t)l * DD * DD;   // [k][n]
    u16* H  = g_WH + (size_t)mat * DD * DD;
    u16* Lo = g_WL + (size_t)mat * DD * DD;
    for (int idx = threadIdx.x; idx < DD * DD; idx += blockDim.x) {
        int k = idx >> 7, n = idx & 127;
        u16 h, lo;
        splitbf(W[idx], h, lo);
        H[n * DD + k] = h;
        Lo[n * DD + k] = lo;
    }
}

// ---------------- split in_feat to bf16 hi/lo ----------------
__global__ void k_split(const float* __restrict__ x, u16* __restrict__ xh, u16* __restrict__ xl) {
    int i = blockIdx.x * blockDim.x + threadIdx.x;      // pairs
    if (i < NN * DD / 2) {
        float2 v = ((const float2*)x)[i];
        u16 h0, l0, h1, l1;
        splitbf(v.x, h0, l0);
        splitbf(v.y, h1, l1);
        ((u32*)xh)[i] = (u32)h0 | ((u32)h1 << 16);
        ((u32*)xl)[i] = (u32)l0 | ((u32)l1 << 16);
    }
}

// ---------------- aggregation: warp per node, writes bf16 hi/lo ----------------
__global__ __launch_bounds__(256) void k_agg(const float* __restrict__ h,
                                             u16* __restrict__ agH, u16* __restrict__ agL) {
    int node = blockIdx.x * 8 + (threadIdx.x >> 5);
    if (node >= NN) return;
    int lane = threadIdx.x & 31;
    int beg = g_rowptr[node], end = g_rowptr[node + 1];
    float ax = 0.f, ay = 0.f, az = 0.f, aw = 0.f;
    int e = beg;
    for (; e + 4 <= end; e += 4) {
        int s0 = __ldg(&g_csr[e + 0]);
        int s1 = __ldg(&g_csr[e + 1]);
        int s2 = __ldg(&g_csr[e + 2]);
        int s3 = __ldg(&g_csr[e + 3]);
        float4 v0 = *(const float4*)(h + (size_t)s0 * DD + lane * 4);
        float4 v1 = *(const float4*)(h + (size_t)s1 * DD + lane * 4);
        float4 v2 = *(const float4*)(h + (size_t)s2 * DD + lane * 4);
        float4 v3 = *(const float4*)(h + (size_t)s3 * DD + lane * 4);
        ax += v0.x + v1.x + v2.x + v3.x;
        ay += v0.y + v1.y + v2.y + v3.y;
        az += v0.z + v1.z + v2.z + v3.z;
        aw += v0.w + v1.w + v2.w + v3.w;
    }
    for (; e < end; e++) {
        int s = __ldg(&g_csr[e]);
        float4 v = *(const float4*)(h + (size_t)s * DD + lane * 4);
        ax += v.x; ay += v.y; az += v.z; aw += v.w;
    }
    u16 hx, lx, hy, ly, hz, lz, hw, lw;
    splitbf(ax, hx, lx); splitbf(ay, hy, ly);
    splitbf(az, hz, lz); splitbf(aw, hw, lw);
    size_t off = (size_t)node * DD + lane * 4;
    *(uint2*)(agH + off) = make_uint2((u32)hx | ((u32)hy << 16), (u32)hz | ((u32)hw << 16));
    *(uint2*)(agL + off) = make_uint2((u32)lx | ((u32)ly << 16), (u32)lz | ((u32)lw << 16));
}

// ---------------- GEMM: bf16 mma.sync 3-term + fused epilogue ----------------
// Static smem stage: {AH, AL, BH, BL} x 128 rows x 80B (64B data + 16B pad).
// OOB A-rows are clamped to row0 (their outputs are masked at store).
// mode 0: +bias  1: +bias,relu,LN  2: +bias,+res,relu,LN
__device__ __forceinline__ void issue_chunk(
    u32 smb, int c, int row0,
    const u16* __restrict__ aH, const u16* __restrict__ aL,
    const u16* __restrict__ bH, const u16* __restrict__ bL, int tid)
{
    const int kg = (c & 3) * 32;
    const int arr = tid >> 6;          // 0:AH 1:AL 2:BH 3:BL
    const bool isA = arr < 2;
    const u16* sp = (arr == 0) ? aH : (arr == 1) ? aL : (arr == 2) ? bH : bL;
    const u32 dbase = smb + arr * 10240;
    const int lt = tid & 63;
    #pragma unroll
    for (int i = 0; i < 8; i++) {
        int seg = i * 64 + lt;              // 0..511
        int row = seg >> 2, q = seg & 3;
        int srow = row;
        if (isA) {
            int grow = row0 + row;
            srow = (grow < NN) ? grow : row0;   // clamp OOB rows (masked at store)
        }
        const char* src = (const char*)sp + ((size_t)srow * DD + kg + q * 8) * 2;
        u32 dst = dbase + row * 80 + q * 16;
        CP16(dst, src);
    }
}

__global__ __launch_bounds__(256, 2) void k_gemm(
    const u16* __restrict__ AH0, const u16* __restrict__ AL0,   // agg hi/lo
    const u16* __restrict__ AH1, const u16* __restrict__ AL1,   // root operand hi/lo
    const float* __restrict__ Hres,                             // residual fp32
    const u16* __restrict__ BH0, const u16* __restrict__ BL0,   // W_rel^T hi/lo
    const u16* __restrict__ BH1, const u16* __restrict__ BL1,   // W_root^T hi/lo
    const float* __restrict__ brel, const float* __restrict__ gamma,
    const float* __restrict__ beta,
    float* __restrict__ out, u16* __restrict__ outH, u16* __restrict__ outL,
    int mode)
{
    __shared__ u32 s_stage[10240];         // 40960 bytes (4 arrays x 2560 u32)
    __shared__ float s_par[3 * DD];
    __shared__ float2 s_red[2][DD];

    const int tid = threadIdx.x;
    const int lane = tid & 31, wid = tid >> 5;
    const int wm = wid & 3, wn = wid >> 2;
    const int g = lane >> 2, t = lane & 3;
    const int row0 = blockIdx.x * 128;
    const u32 smb = smem_u32(s_stage);

    if (tid < DD) {
        s_par[tid]          = brel[tid];
        s_par[DD + tid]     = gamma[tid];
        s_par[2 * DD + tid] = beta[tid];
    }

    float acc[2][8][4];
    #pragma unroll
    for (int i = 0; i < 2; i++)
        #pragma unroll
        for (int j = 0; j < 8; j++)
            #pragma unroll
            for (int q = 0; q < 4; q++) acc[i][j][q] = 0.f;

    for (int c = 0; c < 8; c++) {
        const int mm = c >> 2;
        issue_chunk(smb, c, row0,
                    mm ? AH1 : AH0, mm ? AL1 : AL0,
                    mm ? BH1 : BH0, mm ? BL1 : BL0, tid);
        CP_COMMIT();
        CP_WAIT0();
        __syncthreads();

        const u32* AH32 = s_stage;
        const u32* AL32 = s_stage + 2560;
        const u32* BH32 = s_stage + 5120;
        const u32* BL32 = s_stage + 7680;

        #pragma unroll
        for (int s = 0; s < 2; s++) {
            const int kb = s * 8;
            u32 ah[2][4], al[2][4];
            #pragma unroll
            for (int i = 0; i < 2; i++) {
                int r0 = wm * 32 + i * 16 + g;
                ah[i][0] = AH32[r0 * 20 + kb + t];
                ah[i][1] = AH32[(r0 + 8) * 20 + kb + t];
                ah[i][2] = AH32[r0 * 20 + kb + t + 4];
                ah[i][3] = AH32[(r0 + 8) * 20 + kb + t + 4];
                al[i][0] = AL32[r0 * 20 + kb + t];
                al[i][1] = AL32[(r0 + 8) * 20 + kb + t];
                al[i][2] = AL32[r0 * 20 + kb + t + 4];
                al[i][3] = AL32[(r0 + 8) * 20 + kb + t + 4];
            }
            #pragma unroll
            for (int j = 0; j < 8; j++) {
                int n = wn * 64 + j * 8 + g;
                u32 b0 = BH32[n * 20 + kb + t];
                u32 b1 = BH32[n * 20 + kb + t + 4];
                MMA(acc[0][j], ah[0], b0, b1);
                MMA(acc[1][j], ah[1], b0, b1);
                MMA(acc[0][j], al[0], b0, b1);
                MMA(acc[1][j], al[1], b0, b1);
                u32 c0 = BL32[n * 20 + kb + t];
                u32 c1 = BL32[n * 20 + kb + t + 4];
                MMA(acc[0][j], ah[0], c0, c1);
                MMA(acc[1][j], ah[1], c0, c1);
            }
        }
        __syncthreads();
    }

    // ---------------- epilogue ----------------
    if (mode != 0) {
        #pragma unroll
        for (int i = 0; i < 2; i++)
        #pragma unroll
        for (int p = 0; p < 2; p++) {
            int r = wm * 32 + i * 16 + p * 8 + g;
            int gr = row0 + r;
            float s1 = 0.f, s2 = 0.f;
            #pragma unroll
            for (int j = 0; j < 8; j++) {
                int cc = wn * 64 + j * 8 + 2 * t;
                float v0 = acc[i][j][2 * p]     + s_par[cc];
                float v1 = acc[i][j][2 * p + 1] + s_par[cc + 1];
                if (mode == 2 && gr < NN) {
                    float2 rv = *(const float2*)(Hres + (size_t)gr * DD + cc);
                    v0 += rv.x; v1 += rv.y;
                }
                v0 = fmaxf(v0, 0.f); v1 = fmaxf(v1, 0.f);
                acc[i][j][2 * p] = v0; acc[i][j][2 * p + 1] = v1;
                s1 += v0 + v1; s2 += v0 * v0 + v1 * v1;
            }
            s1 += __shfl_xor_sync(0xffffffffu, s1, 1);
            s1 += __shfl_xor_sync(0xffffffffu, s1, 2);
            s2 += __shfl_xor_sync(0xffffffffu, s2, 1);
            s2 += __shfl_xor_sync(0xffffffffu, s2, 2);
            if (t == 0) s_red[wn][r] = make_float2(s1, s2);
        }
        __syncthreads();
        #pragma unroll
        for (int i = 0; i < 2; i++)
        #pragma unroll
        for (int p = 0; p < 2; p++) {
            int r = wm * 32 + i * 16 + p * 8 + g;
            int gr = row0 + r;
            if (gr >= NN) continue;
            float2 ra = s_red[0][r], rb = s_red[1][r];
            float s1 = ra.x + rb.x, s2 = ra.y + rb.y;
            const float inv = 1.f / (float)DD;
            float mu = s1 * inv;
            float var = fmaxf(s2 * inv - mu * mu, 0.f);
            float rs = rsqrtf(var + EPS);
            #pragma unroll
            for (int j = 0; j < 8; j++) {
                int cc = wn * 64 + j * 8 + 2 * t;
                float v0 = acc[i][j][2 * p], v1 = acc[i][j][2 * p + 1];
                float o0 = (v0 - mu) * rs * s_par[DD + cc]     + s_par[2 * DD + cc];
                float o1 = (v1 - mu) * rs * s_par[DD + cc + 1] + s_par[2 * DD + cc + 1];
                *(float2*)(out + (size_t)gr * DD + cc) = make_float2(o0, o1);
                u16 h0, l0, h1, l1;
                splitbf(o0, h0, l0);
                splitbf(o1, h1, l1);
                *(u32*)(outH + (size_t)gr * DD + cc) = (u32)h0 | ((u32)h1 << 16);
                *(u32*)(outL + (size_t)gr * DD + cc) = (u32)l0 | ((u32)l1 << 16);
            }
        }
    } else {
        __syncthreads();
        #pragma unroll
        for (int i = 0; i < 2; i++)
        #pragma unroll
        for (int p = 0; p < 2; p++) {
            int r = wm * 32 + i * 16 + p * 8 + g;
            int gr = row0 + r;
            if (gr >= NN) continue;
            #pragma unroll
            for (int j = 0; j < 8; j++) {
                int cc = wn * 64 + j * 8 + 2 * t;
                float v0 = acc[i][j][2 * p]     + s_par[cc];
                float v1 = acc[i][j][2 * p + 1] + s_par[cc + 1];
                *(float2*)(out + (size_t)gr * DD + cc) = make_float2(v0, v1);
            }
        }
    }
}

// ---------------- launch ----------------
extern "C" void kernel_launch(void* const* d_in, const int* in_sizes, int n_in,
                              void* d_out, int out_size) {
    const float* in_feat = (const float*)d_in[0];
    const int*   ei      = (const int*)  d_in[1];
    const float* Wrel    = (const float*)d_in[2];
    const float* brel    = (const float*)d_in[3];
    const float* Wroot   = (const float*)d_in[4];
    const float* gamma   = (const float*)d_in[5];
    const float* beta    = (const float*)d_in[6];
    float*       out     = (float*)d_out;

    const int* src = ei;
    const int* dst = ei + EE;

    float *h1, *h2;
    u16 *WH, *WL, *ifH, *ifL, *pAH, *pAL, *pBH, *pBL, *agH, *agL;
    cudaGetSymbolAddress((void**)&h1,  g_h1);
    cudaGetSymbolAddress((void**)&h2,  g_h2);
    cudaGetSymbolAddress((void**)&WH,  g_WH);
    cudaGetSymbolAddress((void**)&WL,  g_WL);
    cudaGetSymbolAddress((void**)&ifH, g_ifH);
    cudaGetSymbolAddress((void**)&ifL, g_ifL);
    cudaGetSymbolAddress((void**)&pAH, g_pAH);
    cudaGetSymbolAddress((void**)&pAL, g_pAL);
    cudaGetSymbolAddress((void**)&pBH, g_pBH);
    cudaGetSymbolAddress((void**)&pBL, g_pBL);
    cudaGetSymbolAddress((void**)&agH, g_agH);
    cudaGetSymbolAddress((void**)&agL, g_agL);

    const int GB = (NN + 127) / 128;
    const int AB = (NN + 7) / 8;
    const int EB = (EE + 255) / 256;
    const int MM = DD * DD;

    k_prep <<<8, 256>>>(Wrel, Wroot);
    k_split<<<(NN * DD / 2 + 255) / 256, 256>>>(in_feat, ifH, ifL);
    k_zero <<<(NN + 255) / 256, 256>>>();
    k_count<<<EB, 256>>>(dst);
    k_scan <<<1, 1024>>>();
    k_fill <<<EB, 256>>>(src, dst);

    // layer 0: conv -> relu -> LN
    k_agg <<<AB, 256>>>(in_feat, agH, agL);
    k_gemm<<<GB, 256>>>(agH, agL, ifH, ifL, in_feat,
                        WH + 0*MM, WL + 0*MM, WH + 1*MM, WL + 1*MM,
                        brel, gamma, beta, h1, pAH, pAL, 1);
    // layer 1: conv -> +res -> relu -> LN
    k_agg <<<AB, 256>>>(h1, agH, agL);
    k_gemm<<<GB, 256>>>(agH, agL, pAH, pAL, h1,
                        WH + 2*MM, WL + 2*MM, WH + 3*MM, WL + 3*MM,
                        brel + DD, gamma, beta, h2, pBH, pBL, 2);
    // layer 2
    k_agg <<<AB, 256>>>(h2, agH, agL);
    k_gemm<<<GB, 256>>>(agH, agL, pBH, pBL, h2,
                        WH + 4*MM, WL + 4*MM, WH + 5*MM, WL + 5*MM,
                        brel + 2*DD, gamma, beta, h1, pAH, pAL, 2);
    // layer 3: conv only
    k_agg <<<AB, 256>>>(h1, agH, agL);
    k_gemm<<<GB, 256>>>(agH, agL, pAH, pAL, h1,
                        WH + 6*MM, WL + 6*MM, WH + 7*MM, WL + 7*MM,
                        brel + 3*DD, gamma, beta, out, pBH, pBL, 0);
}